// round 8
// baseline (speedup 1.0000x reference)
#include <cuda_runtime.h>
#include <math.h>
#include <stdint.h>

#define BB 16
#define TT 64
#define DD 2304
#define HH 2304
#define GG 9216
#define EE 768
#define LANES 32
#define MAXS 32
#define NSTEPS 31
#define KC 144            // K chunks of 16 (2304/16)
#define NTH 144           // step tiles: 16 j x 4 gates = 64 rows each
#define NXB 144           // xp gate blocks of 64
#define NCH 36            // step: K chunks of 64 (4 kc)
#define STG 4             // cp.async pipeline stages
#define STAGE_U32 6144    // Ahi 2048 + Alo 2048 + Bhi 1024 + Blo 1024

// ---------------- device scratch (no runtime allocation) --------------------
__device__ float g_xp [LANES * MAXS * GG];
__device__ float g_h[LANES * HH];            // final h per lane
__device__ float g_c[LANES * HH];
__device__ int   g_len[LANES];
__device__ int   g_length[BB];
__device__ int   g_maxlen;
__device__ int   g_nrows;
__device__ int   g_rows[1024];
// W_hh fragments: [tile(144)][ch(36)][ ((gate*4+kc4)*32+T)*4+a ]  (2048 u32/chunk)
__device__ uint32_t g_whh_hi[NTH * NCH * 2048], g_whh_lo[NTH * NCH * 2048];
// W_ih in B-fragment order: [nblk(144)][kc(144)][T(32)][nt(8)*2+b]
__device__ uint32_t g_wih_hi[NXB * KC * 32 * 16], g_wih_lo[NXB * KC * 32 * 16];
// seq rows in A-fragment order: [mtile(16)][kc(144)][w(4)][T*4+a]
__device__ uint32_t g_a_hi[16 * KC * 4 * 128], g_a_lo[16 * KC * 4 * 128];
// h in B-fragment order, double buffered: [kc(144)][T(32)][nt(4)*2+b]
__device__ uint32_t g_hBhi[2][KC * 32 * 8], g_hBlo[2][KC * 32 * 8];

// ---------------- helpers ---------------------------------------------------
__device__ __forceinline__ uint32_t smem_u32(const void* p) {
    uint32_t a;
    asm("{ .reg .u64 t; cvta.to.shared.u64 t, %1; cvt.u32.u64 %0, t; }" : "=r"(a) : "l"(p));
    return a;
}
// split fp32 pair into packed bf16x2 hi and lo (x -> low half)
__device__ __forceinline__ void split2(float x, float y, uint32_t& hi2, uint32_t& lo2) {
    uint32_t h;
    asm("cvt.rn.bf16x2.f32 %0, %1, %2;" : "=r"(h) : "f"(y), "f"(x));
    float fx = __uint_as_float(h << 16);
    float fy = __uint_as_float(h & 0xffff0000u);
    asm("cvt.rn.bf16x2.f32 %0, %1, %2;" : "=r"(lo2) : "f"(y - fy), "f"(x - fx));
    hi2 = h;
}
__device__ __forceinline__ void mma16816(float* c, const uint32_t* a, const uint32_t* b) {
    asm volatile("mma.sync.aligned.m16n8k16.row.col.f32.bf16.bf16.f32 "
        "{%0,%1,%2,%3}, {%4,%5,%6,%7}, {%8,%9}, {%0,%1,%2,%3};"
        : "+f"(c[0]), "+f"(c[1]), "+f"(c[2]), "+f"(c[3])
        : "r"(a[0]), "r"(a[1]), "r"(a[2]), "r"(a[3]), "r"(b[0]), "r"(b[1]));
}
__device__ __forceinline__ float sigm(float x) { return 1.f / (1.f + expf(-x)); }
#define CP_ASYNC16(saddr, gptr) \
    asm volatile("cp.async.cg.shared.global [%0], [%1], 16;" :: "r"(saddr), "l"(gptr) : "memory")
#define CP_COMMIT() asm volatile("cp.async.commit_group;" ::: "memory")
#define CP_WAIT2()  asm volatile("cp.async.wait_group 2;" ::: "memory")

// ---------------------------------------------------------------------------
// Kernel 0: lengths, compact row list, zero states + hB[0]
// ---------------------------------------------------------------------------
__global__ void k_prep(const int* __restrict__ mask,
                       const int* __restrict__ start,
                       const int* __restrict__ end) {
    int tid = threadIdx.x;
    __shared__ int s_len[LANES];
    if (tid < BB) {
        int L = 0;
        for (int t = 0; t < TT; t++) L += mask[tid * TT + t];
        g_length[tid] = L;
        int ll = start[tid] - 1; if (ll < 1) ll = 1;
        int rl = L - end[tid];   if (rl < 1) rl = 1;
        s_len[tid] = ll;  s_len[BB + tid] = rl;
        g_len[tid] = ll;  g_len[BB + tid] = rl;
    }
    __syncthreads();
    if (tid == 0) {
        int m = 0, n = 0;
        for (int lane = 0; lane < LANES; lane++) {
            int l = s_len[lane];
            if (l > m) m = l;
            for (int t = 0; t < l; t++) g_rows[n++] = (lane << 5) | t;
        }
        g_maxlen = m;
        g_nrows  = n;
    }
    __syncthreads();
    int nr = g_nrows;
    for (int m = nr + tid; m < 1024; m += blockDim.x) g_rows[m] = 0;
    for (int i = tid; i < LANES * HH; i += blockDim.x) { g_h[i] = 0.f; g_c[i] = 0.f; }
    for (int i = tid; i < KC * 32 * 8; i += blockDim.x) {
        g_hBhi[0][i] = 0u;  g_hBlo[0][i] = 0u;
    }
}

// ---------------------------------------------------------------------------
// Kernel 1: W_hh -> per-(tile, 64k-chunk) fragment blocks, coalesced.
// grid (NCH, NTH), block 256. u = gate*128 + kc4*32 + T; thread writes uint4.
// ---------------------------------------------------------------------------
__global__ void __launch_bounds__(256) k_whhprep(const float* __restrict__ W) {
    int ch = blockIdx.x, tile = blockIdx.y;
    int tid = threadIdx.x;
#pragma unroll
    for (int i = 0; i < 2; i++) {
        int u = tid + i * 256;                 // 0..511 (uint4 within hi block)
        int gate = u >> 7, kc4 = (u >> 5) & 3, T = u & 31;
        int kc = ch * 4 + kc4;
        uint32_t hi4[4], lo4[4];
#pragma unroll
        for (int a = 0; a < 4; a++) {
            int rr = (a & 1) * 8 + (T >> 2);
            int kk = (a >> 1) * 8 + (T & 3) * 2;
            int r = gate * HH + tile * 16 + rr;
            float2 v = *(const float2*)(W + (size_t)r * DD + kc * 16 + kk);
            split2(v.x, v.y, hi4[a], lo4[a]);
        }
        size_t base = (size_t)(tile * NCH + ch) * 2048;
        *(uint4*)&g_whh_hi[base + u * 4] = *(uint4*)hi4;
        *(uint4*)&g_whh_lo[base + u * 4] = *(uint4*)lo4;
    }
}

// ---------------------------------------------------------------------------
// Kernel 2: W_ih -> B-fragment order, coalesced writes.
// ---------------------------------------------------------------------------
__global__ void __launch_bounds__(128) k_wihprep(const float* __restrict__ W) {
    int kc = blockIdx.x, nblk = blockIdx.y;
    int tid = threadIdx.x;
    int T = tid >> 2;
    uint32_t hi4[4], lo4[4];
#pragma unroll
    for (int i = 0; i < 4; i++) {
        int r = (tid & 3) * 4 + i;
        int nt = r >> 1, b = r & 1;
        int g = nblk * 64 + nt * 8 + (T >> 2);
        int kk = b * 8 + (T & 3) * 2;
        float2 v = *(const float2*)(W + (size_t)g * DD + kc * 16 + kk);
        split2(v.x, v.y, hi4[i], lo4[i]);
    }
    size_t idx = ((size_t)nblk * KC + kc) * 512 + tid * 4;
    *(uint4*)&g_wih_hi[idx] = *(uint4*)hi4;
    *(uint4*)&g_wih_lo[idx] = *(uint4*)lo4;
}

// ---------------------------------------------------------------------------
// Kernel 3: fused gather + fragment pack of compact seq rows (reads feat)
// ---------------------------------------------------------------------------
__global__ void k_aprep(const float* __restrict__ feat,
                        const int* __restrict__ start,
                        const int* __restrict__ end) {
    int m = blockIdx.y;
    int p = blockIdx.x * blockDim.x + threadIdx.x;
    int k = p * 2;
    int rc = g_rows[m];
    int lane = rc >> 5, t = rc & 31;
    const float* src = nullptr;
    if (lane < BB) {
        int b = lane;
        if (t + 1 < start[b]) src = feat + ((size_t)b * TT + (t + 1)) * DD;
    } else {
        int b = lane - BB;
        int raw = g_length[b] - end[b];
        if (t < raw) src = feat + ((size_t)b * TT + (end[b] + t)) * DD;
    }
    float2 v = make_float2(0.f, 0.f);
    if (src) v = *(const float2*)(src + k);
    int mtile = m >> 6, w = (m & 63) >> 4, rr = m & 15;
    int kc = k >> 4, kk = k & 15;
    int T = (rr & 7) * 4 + ((kk & 7) >> 1);
    int a = (rr >> 3) + 2 * (kk >> 3);
    uint32_t h2, l2; split2(v.x, v.y, h2, l2);
    size_t idx = (((size_t)mtile * KC + kc) * 4 + w) * 128 + T * 4 + a;
    g_a_hi[idx] = h2;
    g_a_lo[idx] = l2;
}

// ---------------------------------------------------------------------------
// Kernel 4: xp GEMM via mma.sync. grid (144 nblk, 16 mtile), block 128.
// ---------------------------------------------------------------------------
__global__ void __launch_bounds__(128) k_xp_mma(const float* __restrict__ b_ih,
                                                const float* __restrict__ b_hh) {
    int nrows = g_nrows;
    int m0 = blockIdx.y * 64;
    if (m0 >= nrows) return;
    int nblk = blockIdx.x;
    int tid = threadIdx.x, w = tid >> 5, T = tid & 31;

    __shared__ int soff[64];
    if (tid < 64) {
        int rc = g_rows[m0 + tid];
        soff[tid] = ((rc >> 5) * MAXS + (rc & 31)) * GG;
    }
    __syncthreads();

    const uint4* Ah = (const uint4*)g_a_hi  + (((size_t)(m0 >> 6) * KC) * 4 + w) * 32 + T;
    const uint4* Al = (const uint4*)g_a_lo  + (((size_t)(m0 >> 6) * KC) * 4 + w) * 32 + T;
    const uint4* Bh = (const uint4*)g_wih_hi + (((size_t)nblk * KC) * 32 + T) * 4;
    const uint4* Bl = (const uint4*)g_wih_lo + (((size_t)nblk * KC) * 32 + T) * 4;

    float acc[8][4];
#pragma unroll
    for (int i = 0; i < 8; i++)
#pragma unroll
        for (int r = 0; r < 4; r++) acc[i][r] = 0.f;

    uint4 ah[2], al[2], bh[2][4], bl[2][4];
#pragma unroll
    for (int q = 0; q < 4; q++) { bh[0][q] = Bh[q]; bl[0][q] = Bl[q]; }
    ah[0] = Ah[0]; al[0] = Al[0];

    for (int kc = 0; kc < KC; kc++) {
        int cur = kc & 1, nxt = cur ^ 1;
        if (kc + 1 < KC) {
            ah[nxt] = Ah[(size_t)(kc + 1) * 128];
            al[nxt] = Al[(size_t)(kc + 1) * 128];
#pragma unroll
            for (int q = 0; q < 4; q++) {
                bh[nxt][q] = Bh[(size_t)(kc + 1) * 128 + q];
                bl[nxt][q] = Bl[(size_t)(kc + 1) * 128 + q];
            }
        }
        const uint32_t* Ahr = (const uint32_t*)&ah[cur];
        const uint32_t* Alr = (const uint32_t*)&al[cur];
        const uint32_t* Bhr = (const uint32_t*)&bh[cur][0];
        const uint32_t* Blr = (const uint32_t*)&bl[cur][0];
#pragma unroll
        for (int nt = 0; nt < 8; nt++) {
            mma16816(acc[nt], Ahr, Bhr + nt * 2);
            mma16816(acc[nt], Ahr, Blr + nt * 2);
            mma16816(acc[nt], Alr, Bhr + nt * 2);
        }
    }

#pragma unroll
    for (int nt = 0; nt < 8; nt++)
#pragma unroll
        for (int r = 0; r < 4; r++) {
            int ml = w * 16 + (T >> 2) + 8 * (r >> 1);
            if (m0 + ml < nrows) {
                int col = nblk * 64 + nt * 8 + 2 * (T & 3) + (r & 1);
                g_xp[(size_t)soff[ml] + col] = acc[nt][r] + b_ih[col] + b_hh[col];
            }
        }
}

// ---------------------------------------------------------------------------
// Kernel 5: one LSTM step — cp.async 4-stage pipelined mma.sync GEMM.
// grid 144, block 256. warp = gate (w&3) x K-half (w>>2: kc4 pairs).
// Stage (24KB): [Ahi 2048 u32][Alo 2048][Bhi 1024][Blo 1024]
// ---------------------------------------------------------------------------
__global__ void __launch_bounds__(256) k_step_mma(int t) {
    if (t >= g_maxlen) return;
    int tile = blockIdx.x;
    int tid = threadIdx.x, w = tid >> 5, T = tid & 31;
    int gate = w & 3, kcH = w >> 2;            // kcH 0..1
    int rb = t & 1, wb = rb ^ 1;

    extern __shared__ __align__(16) uint32_t smem[];     // STG * STAGE_U32
    __shared__ float gsm[64 * 33];
    uint32_t sbase = smem_u32(smem);

    const uint4* Ahg = (const uint4*)g_whh_hi + (size_t)tile * NCH * 512;
    const uint4* Alg = (const uint4*)g_whh_lo + (size_t)tile * NCH * 512;
    const uint4* Bhg = (const uint4*)g_hBhi[rb];
    const uint4* Blg = (const uint4*)g_hBlo[rb];

    auto issue = [&](int ch) {
        uint32_t sb = sbase + (ch & (STG - 1)) * (STAGE_U32 * 4);
#pragma unroll
        for (int q = 0; q < 6; q++) {
            int f = q * 256 + tid;             // uint4 index 0..1535
            const uint4* src;
            if (f < 512)       src = Ahg + (size_t)ch * 512 + f;
            else if (f < 1024) src = Alg + (size_t)ch * 512 + (f - 512);
            else if (f < 1280) src = Bhg + (size_t)ch * 256 + (f - 1024);
            else               src = Blg + (size_t)ch * 256 + (f - 1280);
            CP_ASYNC16(sb + f * 16, src);
        }
    };

    for (int s = 0; s < STG - 1; s++) { issue(s); CP_COMMIT(); }

    float acc[4][4];
#pragma unroll
    for (int i = 0; i < 4; i++)
#pragma unroll
        for (int r = 0; r < 4; r++) acc[i][r] = 0.f;

    for (int ch = 0; ch < NCH; ch++) {
        CP_WAIT2();
        __syncthreads();
        if (ch + STG - 1 < NCH) issue(ch + STG - 1);
        CP_COMMIT();
        const uint32_t* st = smem + (ch & (STG - 1)) * STAGE_U32;
#pragma unroll
        for (int kk = 0; kk < 2; kk++) {
            int kc4 = kcH * 2 + kk;
            uint4 ahi = *(const uint4*)&st[((gate * 4 + kc4) * 32 + T) * 4];
            uint4 alo = *(const uint4*)&st[2048 + ((gate * 4 + kc4) * 32 + T) * 4];
            uint4 b0h = *(const uint4*)&st[4096 + kc4 * 256 + T * 8];
            uint4 b1h = *(const uint4*)&st[4096 + kc4 * 256 + T * 8 + 4];
            uint4 b0l = *(const uint4*)&st[5120 + kc4 * 256 + T * 8];
            uint4 b1l = *(const uint4*)&st[5120 + kc4 * 256 + T * 8 + 4];
            uint32_t bhv[8] = {b0h.x, b0h.y, b0h.z, b0h.w, b1h.x, b1h.y, b1h.z, b1h.w};
            uint32_t blv[8] = {b0l.x, b0l.y, b0l.z, b0l.w, b1l.x, b1l.y, b1l.z, b1l.w};
            const uint32_t* Ahr = (const uint32_t*)&ahi;
            const uint32_t* Alr = (const uint32_t*)&alo;
#pragma unroll
            for (int nt = 0; nt < 4; nt++) {
                mma16816(acc[nt], Ahr, bhv + nt * 2);
                mma16816(acc[nt], Ahr, blv + nt * 2);
                mma16816(acc[nt], Alr, bhv + nt * 2);
            }
        }
    }

    // reduce the two K-halves via SMEM
    if (kcH == 1) {
#pragma unroll
        for (int nt = 0; nt < 4; nt++)
#pragma unroll
            for (int r = 0; r < 4; r++) {
                int rr = (T >> 2) + 8 * (r >> 1);
                int lane = nt * 8 + 2 * (T & 3) + (r & 1);
                gsm[(gate * 16 + rr) * 33 + lane] = acc[nt][r];
            }
    }
    __syncthreads();
    if (kcH == 0) {
#pragma unroll
        for (int nt = 0; nt < 4; nt++)
#pragma unroll
            for (int r = 0; r < 4; r++) {
                int rr = (T >> 2) + 8 * (r >> 1);
                int lane = nt * 8 + 2 * (T & 3) + (r & 1);
                gsm[(gate * 16 + rr) * 33 + lane] += acc[nt][r];
            }
    }
    __syncthreads();

    // pointwise + repack h into B-fragment layout (256 thr = 32 lanes x 8 j-pairs)
    {
        int lane = tid >> 3, jp = tid & 7;
        int jj0 = jp * 2;
        int Tt = (lane & 7) * 4 + ((jj0 & 7) >> 1);
        int nt = lane >> 3, b = jj0 >> 3;
        int idx = tile * 256 + Tt * 8 + nt * 2 + b;
        if (t < g_len[lane]) {
            float hv[2];
            const float* xp = g_xp + ((size_t)(lane * MAXS + t)) * GG;
#pragma unroll
            for (int q = 0; q < 2; q++) {
                int jj = jj0 + q;
                int j = tile * 16 + jj;
                float gi = gsm[(0 * 16 + jj) * 33 + lane] + xp[j];
                float gf = gsm[(1 * 16 + jj) * 33 + lane] + xp[HH + j];
                float gg = gsm[(2 * 16 + jj) * 33 + lane] + xp[2 * HH + j];
                float go = gsm[(3 * 16 + jj) * 33 + lane] + xp[3 * HH + j];
                size_t ci = (size_t)lane * HH + j;
                float cc = sigm(gf) * g_c[ci] + sigm(gi) * tanhf(gg);
                g_c[ci] = cc;
                float h = sigm(go) * tanhf(cc);
                g_h[ci] = h;
                hv[q] = h;
            }
            uint32_t h2, l2; split2(hv[0], hv[1], h2, l2);
            g_hBhi[wb][idx] = h2;
            g_hBlo[wb][idx] = l2;
        } else {
            g_hBhi[wb][idx] = g_hBhi[rb][idx];
            g_hBlo[wb][idx] = g_hBlo[rb][idx];
        }
    }
}

// ---------------------------------------------------------------------------
// Kernel 6: out = [h_left ; h_right] @ W_out^T + b_out
// ---------------------------------------------------------------------------
__global__ void __launch_bounds__(256) k_out(const float* __restrict__ W_out,
                                             const float* __restrict__ b_out,
                                             float* __restrict__ out) {
    int e0 = blockIdx.x * 64;
    int tid = threadIdx.x;
    int eL = tid & 63;
    int bg = tid >> 6;

    __shared__ __align__(16) float Fs[32 * 16];
    __shared__ float Ws[64 * 33];
    float acc[4] = {0.f, 0.f, 0.f, 0.f};

    for (int k0 = 0; k0 < 2 * HH; k0 += 32) {
#pragma unroll
        for (int i = 0; i < 2; i++) {
            int flat = tid + i * 256;
            int b = flat & 15, k = flat >> 4;
            int kk = k0 + k;
            float v = (kk < HH) ? g_h[(size_t)b * HH + kk]
                                : g_h[(size_t)(BB + b) * HH + kk - HH];
            Fs[k * 16 + b] = v;
        }
#pragma unroll
        for (int i = 0; i < 8; i++) {
            int flat = tid + i * 256;
            int e = flat >> 5, k = flat & 31;
            Ws[e * 33 + k] = W_out[(size_t)(e0 + e) * (2 * HH) + k0 + k];
        }
        __syncthreads();
#pragma unroll
        for (int k = 0; k < 32; k++) {
            float wv = Ws[eL * 33 + k];
            float4 f = *(const float4*)&Fs[k * 16 + bg * 4];
            acc[0] += wv * f.x;  acc[1] += wv * f.y;
            acc[2] += wv * f.z;  acc[3] += wv * f.w;
        }
        __syncthreads();
    }
    int e = e0 + eL;
    float bo = b_out[e];
#pragma unroll
    for (int i = 0; i < 4; i++)
        out[(size_t)(bg * 4 + i) * EE + e] = acc[i] + bo;
}

// ---------------------------------------------------------------------------
extern "C" void kernel_launch(void* const* d_in, const int* in_sizes, int n_in,
                              void* d_out, int out_size) {
    const float* feat  = (const float*)d_in[0];
    const int*   mask  = (const int*)  d_in[1];
    const int*   start = (const int*)  d_in[2];
    const int*   end   = (const int*)  d_in[3];
    const float* W_ih  = (const float*)d_in[4];
    const float* W_hh  = (const float*)d_in[5];
    const float* b_ih  = (const float*)d_in[6];
    const float* b_hh  = (const float*)d_in[7];
    const float* W_out = (const float*)d_in[8];
    const float* b_out = (const float*)d_in[9];
    float* out = (float*)d_out;

    const int step_smem = STG * STAGE_U32 * 4;   // 98304 B dynamic
    cudaFuncSetAttribute(k_step_mma, cudaFuncAttributeMaxDynamicSharedMemorySize, step_smem);

    k_prep<<<1, 512>>>(mask, start, end);
    k_whhprep<<<dim3(NCH, NTH), 256>>>(W_hh);
    k_wihprep<<<dim3(KC, NXB), 128>>>(W_ih);
    k_aprep<<<dim3(9, 1024), 128>>>(feat, start, end);
    k_xp_mma<<<dim3(NXB, 16), 128>>>(b_ih, b_hh);
    for (int t = 0; t < NSTEPS; t++)
        k_step_mma<<<NTH, 256, step_smem>>>(t);
    k_out<<<EE / 64, 256>>>(W_out, b_out, out);
}